// round 1
// baseline (speedup 1.0000x reference)
#include <cuda_runtime.h>
#include <cuda_bf16.h>
#include <math.h>

// ---------------- problem constants ----------------
#define SQ     2048
#define HID    2048
#define VOC    32000
#define NHEAD  16
#define NKVH   4
#define HDIM   128
#define FFD    8192
#define NLAYER 4

#define SH  (SQ * HID)          // 4,194,304
#define SKV (SQ * NKVH * HDIM)  // 1,048,576
#define SFF (SQ * FFD)          // 16,777,216

// scratch: h, x, q, attn (SH each), k, v (SKV each), g, u (SFF each)
__device__ float g_scratch[(size_t)4 * SH + 2 * SKV + 2 * SFF];

// ---------------- embedding gather ----------------
__global__ void embed_kernel(const int* __restrict__ ids,
                             const float* __restrict__ emb,
                             float* __restrict__ h) {
    int i = blockIdx.x * blockDim.x + threadIdx.x;  // over SH/4 float4s
    int s = i / (HID / 4);
    int c = i % (HID / 4);
    int tok = ids[s];
    float4 v = ((const float4*)(emb + (size_t)tok * HID))[c];
    ((float4*)(h + (size_t)s * HID))[c] = v;
}

// ---------------- RMSNorm (one block per row, 256 threads) ----------------
__global__ void rmsnorm_kernel(const float* __restrict__ x,
                               const float* __restrict__ w,
                               float* __restrict__ y) {
    int row = blockIdx.x;
    const float4* xr = (const float4*)(x + (size_t)row * HID);
    const float4* wr = (const float4*)w;
    float4* yr = (float4*)(y + (size_t)row * HID);

    float4 v0 = xr[threadIdx.x];
    float4 v1 = xr[threadIdx.x + 256];
    float ss = v0.x * v0.x + v0.y * v0.y + v0.z * v0.z + v0.w * v0.w
             + v1.x * v1.x + v1.y * v1.y + v1.z * v1.z + v1.w * v1.w;

    // block reduce
    __shared__ float red[8];
    for (int o = 16; o > 0; o >>= 1) ss += __shfl_down_sync(0xffffffffu, ss, o);
    if ((threadIdx.x & 31) == 0) red[threadIdx.x >> 5] = ss;
    __syncthreads();
    if (threadIdx.x < 8) {
        float t = red[threadIdx.x];
        for (int o = 4; o > 0; o >>= 1) t += __shfl_down_sync(0xffu, t, o);
        if (threadIdx.x == 0) red[0] = t;
    }
    __syncthreads();
    float inv = rsqrtf(red[0] / (float)HID + 1e-6f);

    float4 w0 = wr[threadIdx.x];
    float4 w1 = wr[threadIdx.x + 256];
    float4 o0, o1;
    o0.x = v0.x * inv * w0.x; o0.y = v0.y * inv * w0.y;
    o0.z = v0.z * inv * w0.z; o0.w = v0.w * inv * w0.w;
    o1.x = v1.x * inv * w1.x; o1.y = v1.y * inv * w1.y;
    o1.z = v1.z * inv * w1.z; o1.w = v1.w * inv * w1.w;
    yr[threadIdx.x] = o0;
    yr[threadIdx.x + 256] = o1;
}

// ---------------- generic SGEMM: C = A[MxK] @ B[KxN] (+bias[N]) (+res[MxN]) ----------------
// BM=BN=128, BK=8, 256 threads, 8x8 register tile. M%128==0, N%128==0, K%8==0.
__global__ __launch_bounds__(256, 2) void sgemm_kernel(
    const float* __restrict__ A, const float* __restrict__ B,
    const float* __restrict__ bias, const float* __restrict__ res,
    float* __restrict__ C, int M, int N, int K) {
    __shared__ float As[8][128];
    __shared__ float Bs[8][128];

    const int bm = blockIdx.y * 128;
    const int bn = blockIdx.x * 128;
    const int tid = threadIdx.x;
    const int tx = tid & 15;   // 0..15 -> cols tx*8
    const int ty = tid >> 4;   // 0..15 -> rows ty*8

    const int arow = tid >> 1;          // 0..127
    const int acol = (tid & 1) * 4;     // 0 or 4
    const int brow = tid >> 5;          // 0..7
    const int bcol = (tid & 31) * 4;    // 0..124

    const float* Aptr = A + (size_t)(bm + arow) * K + acol;
    const float* Bptr = B + (size_t)brow * N + bn + bcol;

    float acc[8][8];
#pragma unroll
    for (int i = 0; i < 8; i++)
#pragma unroll
        for (int j = 0; j < 8; j++) acc[i][j] = 0.f;

    for (int k0 = 0; k0 < K; k0 += 8) {
        float4 a4 = *(const float4*)Aptr;  Aptr += 8;
        float4 b4 = *(const float4*)Bptr;  Bptr += (size_t)8 * N;
        As[acol + 0][arow] = a4.x;
        As[acol + 1][arow] = a4.y;
        As[acol + 2][arow] = a4.z;
        As[acol + 3][arow] = a4.w;
        *(float4*)&Bs[brow][bcol] = b4;
        __syncthreads();
#pragma unroll
        for (int kk = 0; kk < 8; kk++) {
            float a[8], b[8];
            *(float4*)(a)     = *(const float4*)&As[kk][ty * 8];
            *(float4*)(a + 4) = *(const float4*)&As[kk][ty * 8 + 4];
            *(float4*)(b)     = *(const float4*)&Bs[kk][tx * 8];
            *(float4*)(b + 4) = *(const float4*)&Bs[kk][tx * 8 + 4];
#pragma unroll
            for (int i = 0; i < 8; i++)
#pragma unroll
                for (int j = 0; j < 8; j++) acc[i][j] += a[i] * b[j];
        }
        __syncthreads();
    }

#pragma unroll
    for (int i = 0; i < 8; i++) {
        int row = bm + ty * 8 + i;
#pragma unroll
        for (int j = 0; j < 8; j += 4) {
            int col = bn + tx * 8 + j;
            float4 o;
            o.x = acc[i][j + 0]; o.y = acc[i][j + 1];
            o.z = acc[i][j + 2]; o.w = acc[i][j + 3];
            if (bias) {
                float4 bb = *(const float4*)(bias + col);
                o.x += bb.x; o.y += bb.y; o.z += bb.z; o.w += bb.w;
            }
            if (res) {
                float4 rr = *(const float4*)(res + (size_t)row * N + col);
                o.x += rr.x; o.y += rr.y; o.z += rr.z; o.w += rr.w;
            }
            *(float4*)(C + (size_t)row * N + col) = o;
        }
    }
}

// ---------------- RoPE (in place on q and k) ----------------
// grid: (SQ, NHEAD+NKVH), 64 threads (one per rotation pair)
__global__ void rope_kernel(float* __restrict__ q, float* __restrict__ k) {
    int s = blockIdx.x;
    int hh = blockIdx.y;
    int i = threadIdx.x;  // 0..63
    float inv = powf(1000000.0f, -(float)i / 64.0f);
    float f = (float)s * inv;
    float c = cosf(f), sn = sinf(f);
    float* base = (hh < NHEAD)
        ? q + (size_t)s * HID + hh * HDIM
        : k + (size_t)s * (NKVH * HDIM) + (hh - NHEAD) * HDIM;
    float x1 = base[i];
    float x2 = base[i + 64];
    base[i]      = x1 * c - x2 * sn;
    base[i + 64] = x2 * c + x1 * sn;
}

// ---------------- flash attention (causal, GQA 4:1) ----------------
// grid: (NHEAD, SQ/64), 256 threads, dynamic smem.
#define LDQ 132
#define ATTN_SMEM ((3 * 64 * LDQ + 64 * 65 + 3 * 64) * 4)

__global__ __launch_bounds__(256) void attn_kernel(
    const float* __restrict__ q, const float* __restrict__ k,
    const float* __restrict__ v, float* __restrict__ o) {
    extern __shared__ float sm[];
    float* Qs   = sm;
    float* Ks   = Qs + 64 * LDQ;
    float* Vs   = Ks + 64 * LDQ;
    float* Ss   = Vs + 64 * LDQ;     // 64 x 65
    float* Mrow = Ss + 64 * 65;
    float* Lrow = Mrow + 64;
    float* Arow = Lrow + 64;

    const int head = blockIdx.x;
    const int qb   = blockIdx.y;
    const int kvh  = head >> 2;
    const int tid  = threadIdx.x;

    // load Q tile (64 x 128)
    for (int i = tid; i < 64 * 32; i += 256) {
        int r = i >> 5, c4 = (i & 31) << 2;
        *(float4*)(Qs + r * LDQ + c4) =
            *(const float4*)(q + (size_t)(qb * 64 + r) * HID + head * HDIM + c4);
    }
    if (tid < 64) { Mrow[tid] = -1e30f; Lrow[tid] = 0.f; }

    float acc[4][8];
#pragma unroll
    for (int i = 0; i < 4; i++)
#pragma unroll
        for (int j = 0; j < 8; j++) acc[i][j] = 0.f;

    const int i0 = (tid >> 4) * 4;   // 4 query rows
    const int j0 = (tid & 15) * 4;   // 4 key cols (score phase)
    const int d0 = (tid & 15) * 8;   // 8 dims (PV phase)
    const float scale = 0.08838834764831845f;  // 1/sqrt(128)

    for (int kb = 0; kb <= qb; kb++) {
        __syncthreads();  // protect Ks/Vs/Ss from previous-iteration readers
        for (int i = tid; i < 64 * 32; i += 256) {
            int r = i >> 5, c4 = (i & 31) << 2;
            size_t off = (size_t)(kb * 64 + r) * (NKVH * HDIM) + kvh * HDIM + c4;
            *(float4*)(Ks + r * LDQ + c4) = *(const float4*)(k + off);
            *(float4*)(Vs + r * LDQ + c4) = *(const float4*)(v + off);
        }
        __syncthreads();

        // scores: 4x4 per thread
        float sc[4][4];
#pragma unroll
        for (int a = 0; a < 4; a++)
#pragma unroll
            for (int b = 0; b < 4; b++) sc[a][b] = 0.f;
        for (int d4 = 0; d4 < HDIM; d4 += 4) {
            float4 qv[4], kv[4];
#pragma unroll
            for (int a = 0; a < 4; a++) qv[a] = *(const float4*)(Qs + (i0 + a) * LDQ + d4);
#pragma unroll
            for (int b = 0; b < 4; b++) kv[b] = *(const float4*)(Ks + (j0 + b) * LDQ + d4);
#pragma unroll
            for (int a = 0; a < 4; a++)
#pragma unroll
                for (int b = 0; b < 4; b++)
                    sc[a][b] += qv[a].x * kv[b].x + qv[a].y * kv[b].y
                              + qv[a].z * kv[b].z + qv[a].w * kv[b].w;
        }
#pragma unroll
        for (int a = 0; a < 4; a++)
#pragma unroll
            for (int b = 0; b < 4; b++) {
                float val = sc[a][b] * scale;
                if (kb == qb && (j0 + b) > (i0 + a)) val = -1e9f;
                Ss[(i0 + a) * 65 + (j0 + b)] = val;
            }
        __syncthreads();

        // online softmax per row (64 owner threads)
        if (tid < 64) {
            int i = tid;
            float m = Mrow[i];
            float mb = -1e30f;
            for (int j = 0; j < 64; j++) mb = fmaxf(mb, Ss[i * 65 + j]);
            float mn = fmaxf(m, mb);
            float a = expf(m - mn);
            float s = 0.f;
            for (int j = 0; j < 64; j++) {
                float p = expf(Ss[i * 65 + j] - mn);
                Ss[i * 65 + j] = p;
                s += p;
            }
            Lrow[i] = Lrow[i] * a + s;
            Mrow[i] = mn;
            Arow[i] = a;
        }
        __syncthreads();

        // rescale accumulators, then P @ V
#pragma unroll
        for (int a = 0; a < 4; a++) {
            float al = Arow[i0 + a];
#pragma unroll
            for (int d = 0; d < 8; d++) acc[a][d] *= al;
        }
        for (int j = 0; j < 64; j++) {
            float4 v0 = *(const float4*)(Vs + j * LDQ + d0);
            float4 v1 = *(const float4*)(Vs + j * LDQ + d0 + 4);
#pragma unroll
            for (int a = 0; a < 4; a++) {
                float p = Ss[(i0 + a) * 65 + j];
                acc[a][0] += p * v0.x; acc[a][1] += p * v0.y;
                acc[a][2] += p * v0.z; acc[a][3] += p * v0.w;
                acc[a][4] += p * v1.x; acc[a][5] += p * v1.y;
                acc[a][6] += p * v1.z; acc[a][7] += p * v1.w;
            }
        }
    }

#pragma unroll
    for (int a = 0; a < 4; a++) {
        float linv = 1.0f / Lrow[i0 + a];
        int row = qb * 64 + i0 + a;
        float4 o0, o1;
        o0.x = acc[a][0] * linv; o0.y = acc[a][1] * linv;
        o0.z = acc[a][2] * linv; o0.w = acc[a][3] * linv;
        o1.x = acc[a][4] * linv; o1.y = acc[a][5] * linv;
        o1.z = acc[a][6] * linv; o1.w = acc[a][7] * linv;
        *(float4*)(o + (size_t)row * HID + head * HDIM + d0)     = o0;
        *(float4*)(o + (size_t)row * HID + head * HDIM + d0 + 4) = o1;
    }
}

// ---------------- SiLU(g) * u -> g ----------------
__global__ void silu_mul_kernel(float* __restrict__ g, const float* __restrict__ u) {
    int i = blockIdx.x * blockDim.x + threadIdx.x;  // over SFF/4
    float4 gv = ((const float4*)g)[i];
    float4 uv = ((const float4*)u)[i];
    gv.x = gv.x / (1.f + expf(-gv.x)) * uv.x;
    gv.y = gv.y / (1.f + expf(-gv.y)) * uv.y;
    gv.z = gv.z / (1.f + expf(-gv.z)) * uv.z;
    gv.w = gv.w / (1.f + expf(-gv.w)) * uv.w;
    ((float4*)g)[i] = gv;
}

// ---------------- host orchestration ----------------
static void run_sgemm(const float* A, const float* B, const float* bias,
                      const float* res, float* C, int M, int N, int K) {
    dim3 grid(N / 128, M / 128);
    sgemm_kernel<<<grid, 256>>>(A, B, bias, res, C, M, N, K);
}

extern "C" void kernel_launch(void* const* d_in, const int* in_sizes, int n_in,
                              void* d_out, int out_size) {
    const int*   ids    = (const int*)d_in[0];
    const float* emb    = (const float*)d_in[1];
    const float* Wq     = (const float*)d_in[2];
    const float* bq     = (const float*)d_in[3];
    const float* Wk     = (const float*)d_in[4];
    const float* bk     = (const float*)d_in[5];
    const float* Wv     = (const float*)d_in[6];
    const float* bv     = (const float*)d_in[7];
    const float* Wo     = (const float*)d_in[8];
    const float* ln1    = (const float*)d_in[9];
    const float* ln2    = (const float*)d_in[10];
    const float* Wg     = (const float*)d_in[11];
    const float* Wu     = (const float*)d_in[12];
    const float* Wd     = (const float*)d_in[13];
    const float* norm_w = (const float*)d_in[14];
    const float* Wlm    = (const float*)d_in[15];
    const float* blm    = (const float*)d_in[16];
    float* out = (float*)d_out;

    float* base = nullptr;
    cudaGetSymbolAddress((void**)&base, g_scratch);
    float* hbuf = base;
    float* xbuf = base + (size_t)SH;
    float* qbuf = base + (size_t)2 * SH;
    float* abuf = base + (size_t)3 * SH;
    float* kbuf = base + (size_t)4 * SH;
    float* vbuf = kbuf + (size_t)SKV;
    float* gbuf = vbuf + (size_t)SKV;
    float* ubuf = gbuf + (size_t)SFF;

    cudaFuncSetAttribute(attn_kernel, cudaFuncAttributeMaxDynamicSharedMemorySize,
                         ATTN_SMEM);

    embed_kernel<<<SH / 4 / 256, 256>>>(ids, emb, hbuf);

    for (int l = 0; l < NLAYER; l++) {
        const float* Wql = Wq + (size_t)l * HID * HID;
        const float* bql = bq + (size_t)l * HID;
        const float* Wkl = Wk + (size_t)l * HID * (NKVH * HDIM);
        const float* bkl = bk + (size_t)l * (NKVH * HDIM);
        const float* Wvl = Wv + (size_t)l * HID * (NKVH * HDIM);
        const float* bvl = bv + (size_t)l * (NKVH * HDIM);
        const float* Wol = Wo + (size_t)l * HID * HID;
        const float* l1  = ln1 + (size_t)l * HID;
        const float* l2  = ln2 + (size_t)l * HID;
        const float* Wgl = Wg + (size_t)l * HID * FFD;
        const float* Wul = Wu + (size_t)l * HID * FFD;
        const float* Wdl = Wd + (size_t)l * FFD * HID;

        rmsnorm_kernel<<<SQ, 256>>>(hbuf, l1, xbuf);
        run_sgemm(xbuf, Wql, bql, nullptr, qbuf, SQ, HID, HID);
        run_sgemm(xbuf, Wkl, bkl, nullptr, kbuf, SQ, NKVH * HDIM, HID);
        run_sgemm(xbuf, Wvl, bvl, nullptr, vbuf, SQ, NKVH * HDIM, HID);

        dim3 rgrid(SQ, NHEAD + NKVH);
        rope_kernel<<<rgrid, 64>>>(qbuf, kbuf);

        dim3 agrid(NHEAD, SQ / 64);
        attn_kernel<<<agrid, 256, ATTN_SMEM>>>(qbuf, kbuf, vbuf, abuf);

        run_sgemm(abuf, Wol, nullptr, hbuf, hbuf, SQ, HID, HID);  // h += attn @ Wo

        rmsnorm_kernel<<<SQ, 256>>>(hbuf, l2, xbuf);
        run_sgemm(xbuf, Wgl, nullptr, nullptr, gbuf, SQ, FFD, HID);
        run_sgemm(xbuf, Wul, nullptr, nullptr, ubuf, SQ, FFD, HID);
        silu_mul_kernel<<<SFF / 4 / 256, 256>>>(gbuf, ubuf);
        run_sgemm(gbuf, Wdl, nullptr, hbuf, hbuf, SQ, HID, FFD);  // h += mlp
    }

    rmsnorm_kernel<<<SQ, 256>>>(hbuf, norm_w, xbuf);
    run_sgemm(xbuf, Wlm, blm, nullptr, out, SQ, VOC, HID);
}

// round 4
// speedup vs baseline: 2.2402x; 2.2402x over previous
#include <cuda_runtime.h>
#include <cuda_bf16.h>
#include <math.h>
#include <cstdint>

// ---------------- problem constants ----------------
#define SQ     2048
#define HID    2048
#define VOC    32000
#define NHEAD  16
#define NKVH   4
#define HDIM   128
#define FFD    8192
#define NLAYER 4

#define SH  (SQ * HID)
#define SKV (SQ * NKVH * HDIM)
#define SFF (SQ * FFD)

__device__ float g_scratch[(size_t)4 * SH + 2 * SKV + 2 * SFF];

// ======================= helpers =======================
__device__ __forceinline__ uint32_t smem_u32(const void* p) {
    uint32_t a;
    asm("{ .reg .u64 t; cvta.to.shared.u64 t, %1; cvt.u32.u64 %0, t; }"
        : "=r"(a) : "l"(p));
    return a;
}
__device__ __forceinline__ void ldsm_x4(uint32_t* r, uint32_t addr) {
    asm volatile("ldmatrix.sync.aligned.m8n8.x4.shared.b16 {%0,%1,%2,%3}, [%4];"
                 : "=r"(r[0]), "=r"(r[1]), "=r"(r[2]), "=r"(r[3]) : "r"(addr));
}
__device__ __forceinline__ void ldsm_x2t(uint32_t* r, uint32_t addr) {
    asm volatile("ldmatrix.sync.aligned.m8n8.x2.trans.shared.b16 {%0,%1}, [%2];"
                 : "=r"(r[0]), "=r"(r[1]) : "r"(addr));
}
__device__ __forceinline__ void mma_bf16(float* c, const uint32_t* a,
                                         const uint32_t* b) {
    asm volatile("mma.sync.aligned.m16n8k16.row.col.f32.bf16.bf16.f32 "
                 "{%0,%1,%2,%3}, {%4,%5,%6,%7}, {%8,%9}, {%0,%1,%2,%3};"
                 : "+f"(c[0]), "+f"(c[1]), "+f"(c[2]), "+f"(c[3])
                 : "r"(a[0]), "r"(a[1]), "r"(a[2]), "r"(a[3]),
                   "r"(b[0]), "r"(b[1]));
}
__device__ __forceinline__ uint32_t pack2(__nv_bfloat16 a, __nv_bfloat16 b) {
    uint16_t ua = *(uint16_t*)&a, ub = *(uint16_t*)&b;
    return ((uint32_t)ub << 16) | (uint32_t)ua;
}

// ======================= bf16x3 mma.sync GEMM =======================
// C[M,N] = A[M,K] @ W[K,N] (+bias[N]) (+res). BM=BN=128, BK=32, 256 thr.
// Split precision: x = hi + lo (bf16 each); out = hi*hi + hi*lo + lo*hi.
#define ASTRIDE 40    // halves per A smem row (32 + 8 pad)
#define BSTRIDE 152   // halves per B smem k-row (128 + 24 pad)
#define ST_A_HI 0
#define ST_A_LO 10240
#define ST_B_HI 20480
#define ST_B_LO 30208
#define STAGE_BYTES 39936
#define GEMM_SMEM (2 * STAGE_BYTES)

__global__ __launch_bounds__(256, 2) void gemm_bf16x3_kernel(
    const float* __restrict__ A, const float* __restrict__ W,
    const float* __restrict__ bias, const float* __restrict__ res,
    float* __restrict__ C, int M, int N, int K) {
    extern __shared__ char sm[];
    const uint32_t smb = smem_u32(sm);
    const int tid  = threadIdx.x;
    const int lane = tid & 31;
    const int warp = tid >> 5;
    const int wm = warp & 3;       // 4 warps over M (32 rows each)
    const int wn = warp >> 2;      // 2 warps over N (64 cols each)
    const int bm = blockIdx.y * 128;
    const int bn = blockIdx.x * 128;

    // global load assignment
    const int ar = tid >> 1;            // A row 0..127
    const int ak = (tid & 1) * 16;      // A k offset 0/16
    const float* aG = A + (size_t)(bm + ar) * K + ak;
    const int bk = tid >> 3;            // B k-row 0..31
    const int bnoff = (tid & 7) * 16;   // B n offset
    const float* bG = W + (size_t)bk * N + bn + bnoff;

    // smem store byte offsets (within stage)
    const uint32_t aSt = (uint32_t)(ar * ASTRIDE + ak) * 2;
    const uint32_t bSt = (uint32_t)(bk * BSTRIDE + bnoff) * 2;

    // ldmatrix lane base addrs (byte offsets within stage)
    const uint32_t aLd = (uint32_t)(((wm * 32 + (lane & 15)) * ASTRIDE +
                                     ((lane & 16) ? 8 : 0)) * 2);
    const uint32_t bLd = (uint32_t)(((lane & 15) * BSTRIDE + wn * 64) * 2);

    float acc[2][8][4];
#pragma unroll
    for (int i = 0; i < 2; i++)
#pragma unroll
        for (int j = 0; j < 8; j++)
#pragma unroll
            for (int q = 0; q < 4; q++) acc[i][j][q] = 0.f;

    const int nc = K >> 5;

    float4 aR[4], bR[4];
#pragma unroll
    for (int j = 0; j < 4; j++) aR[j] = *(const float4*)(aG + j * 4);
#pragma unroll
    for (int j = 0; j < 4; j++) bR[j] = *(const float4*)(bG + j * 4);

    for (int c = 0; c < nc; c++) {
        // ---- store chunk c (in regs) to stage c&1, converted+split ----
        {
            char* dst = sm + (size_t)(c & 1) * STAGE_BYTES;
#pragma unroll
            for (int j = 0; j < 4; j++) {
                float4 f = aR[j];
                __nv_bfloat16 hx = __float2bfloat16_rn(f.x);
                __nv_bfloat16 hy = __float2bfloat16_rn(f.y);
                __nv_bfloat16 hz = __float2bfloat16_rn(f.z);
                __nv_bfloat16 hw = __float2bfloat16_rn(f.w);
                __nv_bfloat16 lx = __float2bfloat16_rn(f.x - __bfloat162float(hx));
                __nv_bfloat16 ly = __float2bfloat16_rn(f.y - __bfloat162float(hy));
                __nv_bfloat16 lz = __float2bfloat16_rn(f.z - __bfloat162float(hz));
                __nv_bfloat16 lw = __float2bfloat16_rn(f.w - __bfloat162float(hw));
                uint2 hi = make_uint2(pack2(hx, hy), pack2(hz, hw));
                uint2 lo = make_uint2(pack2(lx, ly), pack2(lz, lw));
                *(uint2*)(dst + ST_A_HI + aSt + j * 8) = hi;
                *(uint2*)(dst + ST_A_LO + aSt + j * 8) = lo;
            }
#pragma unroll
            for (int j = 0; j < 4; j++) {
                float4 f = bR[j];
                __nv_bfloat16 hx = __float2bfloat16_rn(f.x);
                __nv_bfloat16 hy = __float2bfloat16_rn(f.y);
                __nv_bfloat16 hz = __float2bfloat16_rn(f.z);
                __nv_bfloat16 hw = __float2bfloat16_rn(f.w);
                __nv_bfloat16 lx = __float2bfloat16_rn(f.x - __bfloat162float(hx));
                __nv_bfloat16 ly = __float2bfloat16_rn(f.y - __bfloat162float(hy));
                __nv_bfloat16 lz = __float2bfloat16_rn(f.z - __bfloat162float(hz));
                __nv_bfloat16 lw = __float2bfloat16_rn(f.w - __bfloat162float(hw));
                uint2 hi = make_uint2(pack2(hx, hy), pack2(hz, hw));
                uint2 lo = make_uint2(pack2(lx, ly), pack2(lz, lw));
                *(uint2*)(dst + ST_B_HI + bSt + j * 8) = hi;
                *(uint2*)(dst + ST_B_LO + bSt + j * 8) = lo;
            }
        }
        __syncthreads();

        // ---- issue gmem loads for chunk c+1 (latency hidden by mma) ----
        if (c + 1 < nc) {
            const float* aP = aG + (c + 1) * 32;
            const float* bP = bG + (size_t)(c + 1) * 32 * N;
#pragma unroll
            for (int j = 0; j < 4; j++) aR[j] = *(const float4*)(aP + j * 4);
#pragma unroll
            for (int j = 0; j < 4; j++) bR[j] = *(const float4*)(bP + j * 4);
        }

        // ---- compute on stage c&1 ----
        const uint32_t sbase = smb + (uint32_t)(c & 1) * STAGE_BYTES;
#pragma unroll
        for (int ks = 0; ks < 2; ks++) {
            uint32_t ah[2][4], al[2][4];
#pragma unroll
            for (int tm = 0; tm < 2; tm++) {
                uint32_t off = aLd + (uint32_t)((tm * 16 * ASTRIDE + ks * 16) * 2);
                ldsm_x4(ah[tm], sbase + ST_A_HI + off);
                ldsm_x4(al[tm], sbase + ST_A_LO + off);
            }
#pragma unroll
            for (int bt = 0; bt < 8; bt++) {
                uint32_t off = bLd + (uint32_t)((ks * 16 * BSTRIDE + bt * 8) * 2);
                uint32_t bh[2], bl[2];
                ldsm_x2t(bh, sbase + ST_B_HI + off);
                ldsm_x2t(bl, sbase + ST_B_LO + off);
#pragma unroll
                for (int tm = 0; tm < 2; tm++) {
                    mma_bf16(acc[tm][bt], ah[tm], bh);
                    mma_bf16(acc[tm][bt], ah[tm], bl);
                    mma_bf16(acc[tm][bt], al[tm], bh);
                }
            }
        }
        __syncthreads();
    }

    // ---- epilogue ----
#pragma unroll
    for (int tm = 0; tm < 2; tm++) {
#pragma unroll
        for (int bt = 0; bt < 8; bt++) {
            int r0  = bm + wm * 32 + tm * 16 + (lane >> 2);
            int col = bn + wn * 64 + bt * 8 + (lane & 3) * 2;
            float2 v0 = make_float2(acc[tm][bt][0], acc[tm][bt][1]);
            float2 v1 = make_float2(acc[tm][bt][2], acc[tm][bt][3]);
            if (bias) {
                float2 bb = *(const float2*)(bias + col);
                v0.x += bb.x; v0.y += bb.y;
                v1.x += bb.x; v1.y += bb.y;
            }
            if (res) {
                float2 r0v = *(const float2*)(res + (size_t)r0 * N + col);
                float2 r1v = *(const float2*)(res + (size_t)(r0 + 8) * N + col);
                v0.x += r0v.x; v0.y += r0v.y;
                v1.x += r1v.x; v1.y += r1v.y;
            }
            *(float2*)(C + (size_t)r0 * N + col) = v0;
            *(float2*)(C + (size_t)(r0 + 8) * N + col) = v1;
        }
    }
}

// ---------------- embedding gather ----------------
__global__ void embed_kernel(const int* __restrict__ ids,
                             const float* __restrict__ emb,
                             float* __restrict__ h) {
    int i = blockIdx.x * blockDim.x + threadIdx.x;
    int s = i / (HID / 4);
    int c = i % (HID / 4);
    int tok = ids[s];
    float4 v = ((const float4*)(emb + (size_t)tok * HID))[c];
    ((float4*)(h + (size_t)s * HID))[c] = v;
}

// ---------------- RMSNorm ----------------
__global__ void rmsnorm_kernel(const float* __restrict__ x,
                               const float* __restrict__ w,
                               float* __restrict__ y) {
    int row = blockIdx.x;
    const float4* xr = (const float4*)(x + (size_t)row * HID);
    const float4* wr = (const float4*)w;
    float4* yr = (float4*)(y + (size_t)row * HID);

    float4 v0 = xr[threadIdx.x];
    float4 v1 = xr[threadIdx.x + 256];
    float ss = v0.x * v0.x + v0.y * v0.y + v0.z * v0.z + v0.w * v0.w
             + v1.x * v1.x + v1.y * v1.y + v1.z * v1.z + v1.w * v1.w;

    __shared__ float red[8];
    for (int o = 16; o > 0; o >>= 1) ss += __shfl_down_sync(0xffffffffu, ss, o);
    if ((threadIdx.x & 31) == 0) red[threadIdx.x >> 5] = ss;
    __syncthreads();
    if (threadIdx.x < 8) {
        float t = red[threadIdx.x];
        for (int o = 4; o > 0; o >>= 1) t += __shfl_down_sync(0xffu, t, o);
        if (threadIdx.x == 0) red[0] = t;
    }
    __syncthreads();
    float inv = rsqrtf(red[0] / (float)HID + 1e-6f);

    float4 w0 = wr[threadIdx.x];
    float4 w1 = wr[threadIdx.x + 256];
    float4 o0, o1;
    o0.x = v0.x * inv * w0.x; o0.y = v0.y * inv * w0.y;
    o0.z = v0.z * inv * w0.z; o0.w = v0.w * inv * w0.w;
    o1.x = v1.x * inv * w1.x; o1.y = v1.y * inv * w1.y;
    o1.z = v1.z * inv * w1.z; o1.w = v1.w * inv * w1.w;
    yr[threadIdx.x] = o0;
    yr[threadIdx.x + 256] = o1;
}

// ---------------- RoPE ----------------
__global__ void rope_kernel(float* __restrict__ q, float* __restrict__ k) {
    int s = blockIdx.x;
    int hh = blockIdx.y;
    int i = threadIdx.x;
    float inv = powf(1000000.0f, -(float)i / 64.0f);
    float f = (float)s * inv;
    float c = cosf(f), sn = sinf(f);
    float* base = (hh < NHEAD)
        ? q + (size_t)s * HID + hh * HDIM
        : k + (size_t)s * (NKVH * HDIM) + (hh - NHEAD) * HDIM;
    float x1 = base[i];
    float x2 = base[i + 64];
    base[i]      = x1 * c - x2 * sn;
    base[i + 64] = x2 * c + x1 * sn;
}

// ---------------- flash attention (fp32 SIMT, causal, GQA) ----------------
#define LDQ 132
#define ATTN_SMEM ((3 * 64 * LDQ + 64 * 65 + 3 * 64) * 4)

__global__ __launch_bounds__(256) void attn_kernel(
    const float* __restrict__ q, const float* __restrict__ k,
    const float* __restrict__ v, float* __restrict__ o) {
    extern __shared__ float smf[];
    float* Qs   = smf;
    float* Ks   = Qs + 64 * LDQ;
    float* Vs   = Ks + 64 * LDQ;
    float* Ss   = Vs + 64 * LDQ;
    float* Mrow = Ss + 64 * 65;
    float* Lrow = Mrow + 64;
    float* Arow = Lrow + 64;

    const int head = blockIdx.x;
    const int qb   = blockIdx.y;
    const int kvh  = head >> 2;
    const int tid  = threadIdx.x;

    for (int i = tid; i < 64 * 32; i += 256) {
        int r = i >> 5, c4 = (i & 31) << 2;
        *(float4*)(Qs + r * LDQ + c4) =
            *(const float4*)(q + (size_t)(qb * 64 + r) * HID + head * HDIM + c4);
    }
    if (tid < 64) { Mrow[tid] = -1e30f; Lrow[tid] = 0.f; }

    float acc[4][8];
#pragma unroll
    for (int i = 0; i < 4; i++)
#pragma unroll
        for (int j = 0; j < 8; j++) acc[i][j] = 0.f;

    const int i0 = (tid >> 4) * 4;
    const int j0 = (tid & 15) * 4;
    const int d0 = (tid & 15) * 8;
    const float scale = 0.08838834764831845f;

    for (int kb = 0; kb <= qb; kb++) {
        __syncthreads();
        for (int i = tid; i < 64 * 32; i += 256) {
            int r = i >> 5, c4 = (i & 31) << 2;
            size_t off = (size_t)(kb * 64 + r) * (NKVH * HDIM) + kvh * HDIM + c4;
            *(float4*)(Ks + r * LDQ + c4) = *(const float4*)(k + off);
            *(float4*)(Vs + r * LDQ + c4) = *(const float4*)(v + off);
        }
        __syncthreads();

        float sc[4][4];
#pragma unroll
        for (int a = 0; a < 4; a++)
#pragma unroll
            for (int b = 0; b < 4; b++) sc[a][b] = 0.f;
        for (int d4 = 0; d4 < HDIM; d4 += 4) {
            float4 qv[4], kv[4];
#pragma unroll
            for (int a = 0; a < 4; a++) qv[a] = *(const float4*)(Qs + (i0 + a) * LDQ + d4);
#pragma unroll
            for (int b = 0; b < 4; b++) kv[b] = *(const float4*)(Ks + (j0 + b) * LDQ + d4);
#pragma unroll
            for (int a = 0; a < 4; a++)
#pragma unroll
                for (int b = 0; b < 4; b++)
                    sc[a][b] += qv[a].x * kv[b].x + qv[a].y * kv[b].y
                              + qv[a].z * kv[b].z + qv[a].w * kv[b].w;
        }
#pragma unroll
        for (int a = 0; a < 4; a++)
#pragma unroll
            for (int b = 0; b < 4; b++) {
                float val = sc[a][b] * scale;
                if (kb == qb && (j0 + b) > (i0 + a)) val = -1e9f;
                Ss[(i0 + a) * 65 + (j0 + b)] = val;
            }
        __syncthreads();

        if (tid < 64) {
            int i = tid;
            float m = Mrow[i];
            float mb = -1e30f;
            for (int j = 0; j < 64; j++) mb = fmaxf(mb, Ss[i * 65 + j]);
            float mn = fmaxf(m, mb);
            float a = expf(m - mn);
            float s = 0.f;
            for (int j = 0; j < 64; j++) {
                float p = expf(Ss[i * 65 + j] - mn);
                Ss[i * 65 + j] = p;
                s += p;
            }
            Lrow[i] = Lrow[i] * a + s;
            Mrow[i] = mn;
            Arow[i] = a;
        }
        __syncthreads();

#pragma unroll
        for (int a = 0; a < 4; a++) {
            float al = Arow[i0 + a];
#pragma unroll
            for (int d = 0; d < 8; d++) acc[a][d] *= al;
        }
        for (int j = 0; j < 64; j++) {
            float4 v0 = *(const float4*)(Vs + j * LDQ + d0);
            float4 v1 = *(const float4*)(Vs + j * LDQ + d0 + 4);
#pragma unroll
            for (int a = 0; a < 4; a++) {
                float p = Ss[(i0 + a) * 65 + j];
                acc[a][0] += p * v0.x; acc[a][1] += p * v0.y;
                acc[a][2] += p * v0.z; acc[a][3] += p * v0.w;
                acc[a][4] += p * v1.x; acc[a][5] += p * v1.y;
                acc[a][6] += p * v1.z; acc[a][7] += p * v1.w;
            }
        }
    }

#pragma unroll
    for (int a = 0; a < 4; a++) {
        float linv = 1.0f / Lrow[i0 + a];
        int row = qb * 64 + i0 + a;
        float4 o0, o1;
        o0.x = acc[a][0] * linv; o0.y = acc[a][1] * linv;
        o0.z = acc[a][2] * linv; o0.w = acc[a][3] * linv;
        o1.x = acc[a][4] * linv; o1.y = acc[a][5] * linv;
        o1.z = acc[a][6] * linv; o1.w = acc[a][7] * linv;
        *(float4*)(o + (size_t)row * HID + head * HDIM + d0)     = o0;
        *(float4*)(o + (size_t)row * HID + head * HDIM + d0 + 4) = o1;
    }
}

// ---------------- SiLU(g) * u -> g ----------------
__global__ void silu_mul_kernel(float* __restrict__ g, const float* __restrict__ u) {
    int i = blockIdx.x * blockDim.x + threadIdx.x;
    float4 gv = ((const float4*)g)[i];
    float4 uv = ((const float4*)u)[i];
    gv.x = gv.x / (1.f + expf(-gv.x)) * uv.x;
    gv.y = gv.y / (1.f + expf(-gv.y)) * uv.y;
    gv.z = gv.z / (1.f + expf(-gv.z)) * uv.z;
    gv.w = gv.w / (1.f + expf(-gv.w)) * uv.w;
    ((float4*)g)[i] = gv;
}

// ---------------- host orchestration ----------------
static void run_gemm(const float* A, const float* W, const float* bias,
                     const float* res, float* C, int M, int N, int K) {
    dim3 grid(N / 128, M / 128);
    gemm_bf16x3_kernel<<<grid, 256, GEMM_SMEM>>>(A, W, bias, res, C, M, N, K);
}

extern "C" void kernel_launch(void* const* d_in, const int* in_sizes, int n_in,
                              void* d_out, int out_size) {
    const int*   ids    = (const int*)d_in[0];
    const float* emb    = (const float*)d_in[1];
    const float* Wq     = (const float*)d_in[2];
    const float* bq     = (const float*)d_in[3];
    const float* Wk     = (const float*)d_in[4];
    const float* bk     = (const float*)d_in[5];
    const float* Wv     = (const float*)d_in[6];
    const float* bv     = (const float*)d_in[7];
    const float* Wo     = (const float*)d_in[8];
    const float* ln1    = (const float*)d_in[9];
    const float* ln2    = (const float*)d_in[10];
    const float* Wg     = (const float*)d_in[11];
    const float* Wu     = (const float*)d_in[12];
    const float* Wd     = (const float*)d_in[13];
    const float* norm_w = (const float*)d_in[14];
    const float* Wlm    = (const float*)d_in[15];
    const float* blm    = (const float*)d_in[16];
    float* out = (float*)d_out;

    float* base = nullptr;
    cudaGetSymbolAddress((void**)&base, g_scratch);
    float* hbuf = base;
    float* xbuf = base + (size_t)SH;
    float* qbuf = base + (size_t)2 * SH;
    float* abuf = base + (size_t)3 * SH;
    float* kbuf = base + (size_t)4 * SH;
    float* vbuf = kbuf + (size_t)SKV;
    float* gbuf = vbuf + (size_t)SKV;
    float* ubuf = gbuf + (size_t)SFF;

    cudaFuncSetAttribute(attn_kernel, cudaFuncAttributeMaxDynamicSharedMemorySize,
                         ATTN_SMEM);
    cudaFuncSetAttribute(gemm_bf16x3_kernel,
                         cudaFuncAttributeMaxDynamicSharedMemorySize, GEMM_SMEM);

    embed_kernel<<<SH / 4 / 256, 256>>>(ids, emb, hbuf);

    for (int l = 0; l < NLAYER; l++) {
        const float* Wql = Wq + (size_t)l * HID * HID;
        const float* bql = bq + (size_t)l * HID;
        const float* Wkl = Wk + (size_t)l * HID * (NKVH * HDIM);
        const float* bkl = bk + (size_t)l * (NKVH * HDIM);
        const float* Wvl = Wv + (size_t)l * HID * (NKVH * HDIM);
        const float* bvl = bv + (size_t)l * (NKVH * HDIM);
        const float* Wol = Wo + (size_t)l * HID * HID;
        const float* l1  = ln1 + (size_t)l * HID;
        const float* l2  = ln2 + (size_t)l * HID;
        const float* Wgl = Wg + (size_t)l * HID * FFD;
        const float* Wul = Wu + (size_t)l * HID * FFD;
        const float* Wdl = Wd + (size_t)l * FFD * HID;

        rmsnorm_kernel<<<SQ, 256>>>(hbuf, l1, xbuf);
        run_gemm(xbuf, Wql, bql, nullptr, qbuf, SQ, HID, HID);
        run_gemm(xbuf, Wkl, bkl, nullptr, kbuf, SQ, NKVH * HDIM, HID);
        run_gemm(xbuf, Wvl, bvl, nullptr, vbuf, SQ, NKVH * HDIM, HID);

        dim3 rgrid(SQ, NHEAD + NKVH);
        rope_kernel<<<rgrid, 64>>>(qbuf, kbuf);

        dim3 agrid(NHEAD, SQ / 64);
        attn_kernel<<<agrid, 256, ATTN_SMEM>>>(qbuf, kbuf, vbuf, abuf);

        run_gemm(abuf, Wol, nullptr, hbuf, hbuf, SQ, HID, HID);

        rmsnorm_kernel<<<SQ, 256>>>(hbuf, l2, xbuf);
        run_gemm(xbuf, Wgl, nullptr, nullptr, gbuf, SQ, FFD, HID);
        run_gemm(xbuf, Wul, nullptr, nullptr, ubuf, SQ, FFD, HID);
        silu_mul_kernel<<<SFF / 4 / 256, 256>>>(gbuf, ubuf);
        run_gemm(gbuf, Wdl, nullptr, hbuf, hbuf, SQ, HID, FFD);
    }

    rmsnorm_kernel<<<SQ, 256>>>(hbuf, norm_w, xbuf);
    run_gemm(xbuf, Wlm, blm, nullptr, out, SQ, VOC, HID);
}

// round 5
// speedup vs baseline: 2.4295x; 1.0845x over previous
#include <cuda_runtime.h>
#include <cuda_bf16.h>
#include <math.h>
#include <cstdint>

// ---------------- problem constants ----------------
#define SQ     2048
#define HID    2048
#define VOC    32000
#define NHEAD  16
#define NKVH   4
#define HDIM   128
#define FFD    8192
#define NLAYER 4

#define SH  (SQ * HID)
#define SKV (SQ * NKVH * HDIM)
#define SFF (SQ * FFD)

__device__ float g_scratch[(size_t)4 * SH + 2 * SKV + 2 * SFF];
__device__ __nv_bfloat16 g_ahi[(size_t)SFF];
__device__ __nv_bfloat16 g_alo[(size_t)SFF];
__device__ __nv_bfloat16 g_whi[(size_t)HID * VOC];
__device__ __nv_bfloat16 g_wlo[(size_t)HID * VOC];

// ======================= helpers =======================
__device__ __forceinline__ uint32_t smem_u32(const void* p) {
    uint32_t a;
    asm("{ .reg .u64 t; cvta.to.shared.u64 t, %1; cvt.u32.u64 %0, t; }"
        : "=r"(a) : "l"(p));
    return a;
}
__device__ __forceinline__ void ldsm_x4(uint32_t* r, uint32_t addr) {
    asm volatile("ldmatrix.sync.aligned.m8n8.x4.shared.b16 {%0,%1,%2,%3}, [%4];"
                 : "=r"(r[0]), "=r"(r[1]), "=r"(r[2]), "=r"(r[3]) : "r"(addr));
}
__device__ __forceinline__ void ldsm_x4t(uint32_t* r, uint32_t addr) {
    asm volatile("ldmatrix.sync.aligned.m8n8.x4.trans.shared.b16 {%0,%1,%2,%3}, [%4];"
                 : "=r"(r[0]), "=r"(r[1]), "=r"(r[2]), "=r"(r[3]) : "r"(addr));
}
__device__ __forceinline__ void mma_bf16(float* c, const uint32_t* a,
                                         const uint32_t* b) {
    asm volatile("mma.sync.aligned.m16n8k16.row.col.f32.bf16.bf16.f32 "
                 "{%0,%1,%2,%3}, {%4,%5,%6,%7}, {%8,%9}, {%0,%1,%2,%3};"
                 : "+f"(c[0]), "+f"(c[1]), "+f"(c[2]), "+f"(c[3])
                 : "r"(a[0]), "r"(a[1]), "r"(a[2]), "r"(a[3]),
                   "r"(b[0]), "r"(b[1]));
}
__device__ __forceinline__ uint32_t pack2(__nv_bfloat16 a, __nv_bfloat16 b) {
    uint16_t ua = *(uint16_t*)&a, ub = *(uint16_t*)&b;
    return ((uint32_t)ub << 16) | (uint32_t)ua;
}
#define CP16(dst, src) \
    asm volatile("cp.async.cg.shared.global [%0], [%1], 16;" :: "r"(dst), "l"(src))
#define CP_COMMIT() asm volatile("cp.async.commit_group;" ::: "memory")

// ---------------- split: fp32 -> bf16 hi/lo planes ----------------
__global__ void split_kernel(const float* __restrict__ src,
                             __nv_bfloat16* __restrict__ hi,
                             __nv_bfloat16* __restrict__ lo, int n4) {
    int i = blockIdx.x * blockDim.x + threadIdx.x;
    if (i >= n4) return;
    float4 f = ((const float4*)src)[i];
    __nv_bfloat16 hx = __float2bfloat16_rn(f.x);
    __nv_bfloat16 hy = __float2bfloat16_rn(f.y);
    __nv_bfloat16 hz = __float2bfloat16_rn(f.z);
    __nv_bfloat16 hw = __float2bfloat16_rn(f.w);
    __nv_bfloat16 lx = __float2bfloat16_rn(f.x - __bfloat162float(hx));
    __nv_bfloat16 ly = __float2bfloat16_rn(f.y - __bfloat162float(hy));
    __nv_bfloat16 lz = __float2bfloat16_rn(f.z - __bfloat162float(hz));
    __nv_bfloat16 lw = __float2bfloat16_rn(f.w - __bfloat162float(hw));
    ((uint2*)hi)[i] = make_uint2(pack2(hx, hy), pack2(hz, hw));
    ((uint2*)lo)[i] = make_uint2(pack2(lx, ly), pack2(lz, lw));
}

// ======================= pre-split bf16x3 GEMM with cp.async =======================
// C[M,N] = A[M,K] @ W[K,N] (+bias)(+res). BN=128, BK=32. BM template (128/256).
// smem per stage: Ahi/Alo rows stride 80B; Bhi/Blo k-rows stride 304B.
template<int BM, int NSTAGE>
__global__ __launch_bounds__(BM * 2, (BM == 128) ? 2 : 1)
void gemm_ps_kernel(const __nv_bfloat16* __restrict__ Ahi,
                    const __nv_bfloat16* __restrict__ Alo,
                    const __nv_bfloat16* __restrict__ Whi,
                    const __nv_bfloat16* __restrict__ Wlo,
                    const float* __restrict__ bias, const float* __restrict__ res,
                    float* __restrict__ C, int M, int N, int K) {
    constexpr int NTHR = BM * 2;
    constexpr int NWM  = BM / 32;
    constexpr uint32_t ST_A_LO = (uint32_t)BM * 80u;
    constexpr uint32_t ST_B_HI = 2u * BM * 80u;
    constexpr uint32_t ST_B_LO = ST_B_HI + 9728u;
    constexpr uint32_t STAGE   = ST_B_LO + 9728u;

    extern __shared__ char sm[];
    const uint32_t smb = smem_u32(sm);
    const int tid  = threadIdx.x;
    const int lane = tid & 31;
    const int warp = tid >> 5;
    const int wm = warp % NWM;
    const int wn = warp / NWM;
    const int bm = blockIdx.y * BM;
    const int bn = blockIdx.x * 128;

    const uint32_t aLd = (uint32_t)((wm * 32 + (lane & 15)) * 80 +
                                    ((lane >> 4) & 1) * 16);
    const uint32_t bLd = (uint32_t)((lane & 15) * 304 + (lane >> 4) * 16 +
                                    wn * 128);

    float acc[2][8][4];
#pragma unroll
    for (int i = 0; i < 2; i++)
#pragma unroll
        for (int j = 0; j < 8; j++)
#pragma unroll
            for (int q = 0; q < 4; q++) acc[i][j][q] = 0.f;

    const int nc = K >> 5;

    auto issue = [&](int c, int stg) {
        if (c < nc) {
            const uint32_t st = smb + (uint32_t)stg * STAGE;
            const size_t kof = (size_t)c * 32;
#pragma unroll
            for (int i = 0; i < 2; i++) {
                int id = tid + i * NTHR;
                int r = id >> 2, cc = id & 3;
                uint32_t d = st + (uint32_t)(r * 80 + cc * 16);
                size_t so = (size_t)(bm + r) * K + kof + cc * 8;
                CP16(d, Ahi + so);
                CP16(d + ST_A_LO, Alo + so);
            }
            constexpr int NB = 512 / NTHR;
#pragma unroll
            for (int i = 0; i < (NB ? NB : 1); i++) {
                int id = tid + i * NTHR;
                if (NB == 0 && id >= 512) break;
                int kr = id >> 4, ncc = id & 15;
                uint32_t d = st + ST_B_HI + (uint32_t)(kr * 304 + ncc * 16);
                size_t so = (size_t)(kof + kr) * N + bn + ncc * 8;
                CP16(d, Whi + so);
                CP16(d + 9728u, Wlo + so);
            }
        }
        CP_COMMIT();
    };

#pragma unroll
    for (int s = 0; s < NSTAGE; s++) issue(s, s);

    int rd = 0;
    for (int c = 0; c < nc; c++) {
        asm volatile("cp.async.wait_group %0;" :: "n"(NSTAGE - 1) : "memory");
        __syncthreads();
        const uint32_t sb = smb + (uint32_t)rd * STAGE;
#pragma unroll
        for (int ks = 0; ks < 2; ks++) {
            uint32_t ah[2][4], al[2][4];
#pragma unroll
            for (int tm = 0; tm < 2; tm++) {
                uint32_t off = aLd + (uint32_t)(tm * 16 * 80 + ks * 32);
                ldsm_x4(ah[tm], sb + off);
                ldsm_x4(al[tm], sb + ST_A_LO + off);
            }
#pragma unroll
            for (int p = 0; p < 4; p++) {
                uint32_t off = bLd + (uint32_t)(ks * 16 * 304 + p * 32);
                uint32_t bh[4], bl[4];
                ldsm_x4t(bh, sb + ST_B_HI + off);
                ldsm_x4t(bl, sb + ST_B_LO + off);
#pragma unroll
                for (int h = 0; h < 2; h++) {
#pragma unroll
                    for (int tm = 0; tm < 2; tm++) {
                        mma_bf16(acc[tm][p * 2 + h], ah[tm], bh + 2 * h);
                        mma_bf16(acc[tm][p * 2 + h], ah[tm], bl + 2 * h);
                        mma_bf16(acc[tm][p * 2 + h], al[tm], bh + 2 * h);
                    }
                }
            }
        }
        __syncthreads();
        issue(c + NSTAGE, rd);
        rd = (rd + 1 == NSTAGE) ? 0 : rd + 1;
    }

    // ---- epilogue ----
#pragma unroll
    for (int tm = 0; tm < 2; tm++) {
#pragma unroll
        for (int bt = 0; bt < 8; bt++) {
            int r0  = bm + wm * 32 + tm * 16 + (lane >> 2);
            int col = bn + wn * 64 + bt * 8 + (lane & 3) * 2;
            float2 v0 = make_float2(acc[tm][bt][0], acc[tm][bt][1]);
            float2 v1 = make_float2(acc[tm][bt][2], acc[tm][bt][3]);
            if (bias) {
                float2 bb = *(const float2*)(bias + col);
                v0.x += bb.x; v0.y += bb.y;
                v1.x += bb.x; v1.y += bb.y;
            }
            if (res) {
                float2 r0v = *(const float2*)(res + (size_t)r0 * N + col);
                float2 r1v = *(const float2*)(res + (size_t)(r0 + 8) * N + col);
                v0.x += r0v.x; v0.y += r0v.y;
                v1.x += r1v.x; v1.y += r1v.y;
            }
            *(float2*)(C + (size_t)r0 * N + col) = v0;
            *(float2*)(C + (size_t)(r0 + 8) * N + col) = v1;
        }
    }
}

// ---------------- embedding gather ----------------
__global__ void embed_kernel(const int* __restrict__ ids,
                             const float* __restrict__ emb,
                             float* __restrict__ h) {
    int i = blockIdx.x * blockDim.x + threadIdx.x;
    int s = i / (HID / 4);
    int c = i % (HID / 4);
    int tok = ids[s];
    float4 v = ((const float4*)(emb + (size_t)tok * HID))[c];
    ((float4*)(h + (size_t)s * HID))[c] = v;
}

// ---------------- RMSNorm ----------------
__global__ void rmsnorm_kernel(const float* __restrict__ x,
                               const float* __restrict__ w,
                               float* __restrict__ y) {
    int row = blockIdx.x;
    const float4* xr = (const float4*)(x + (size_t)row * HID);
    const float4* wr = (const float4*)w;
    float4* yr = (float4*)(y + (size_t)row * HID);

    float4 v0 = xr[threadIdx.x];
    float4 v1 = xr[threadIdx.x + 256];
    float ss = v0.x * v0.x + v0.y * v0.y + v0.z * v0.z + v0.w * v0.w
             + v1.x * v1.x + v1.y * v1.y + v1.z * v1.z + v1.w * v1.w;

    __shared__ float red[8];
    for (int o = 16; o > 0; o >>= 1) ss += __shfl_down_sync(0xffffffffu, ss, o);
    if ((threadIdx.x & 31) == 0) red[threadIdx.x >> 5] = ss;
    __syncthreads();
    if (threadIdx.x < 8) {
        float t = red[threadIdx.x];
        for (int o = 4; o > 0; o >>= 1) t += __shfl_down_sync(0xffu, t, o);
        if (threadIdx.x == 0) red[0] = t;
    }
    __syncthreads();
    float inv = rsqrtf(red[0] / (float)HID + 1e-6f);

    float4 w0 = wr[threadIdx.x];
    float4 w1 = wr[threadIdx.x + 256];
    float4 o0, o1;
    o0.x = v0.x * inv * w0.x; o0.y = v0.y * inv * w0.y;
    o0.z = v0.z * inv * w0.z; o0.w = v0.w * inv * w0.w;
    o1.x = v1.x * inv * w1.x; o1.y = v1.y * inv * w1.y;
    o1.z = v1.z * inv * w1.z; o1.w = v1.w * inv * w1.w;
    yr[threadIdx.x] = o0;
    yr[threadIdx.x + 256] = o1;
}

// ---------------- RoPE ----------------
__global__ void rope_kernel(float* __restrict__ q, float* __restrict__ k) {
    int s = blockIdx.x;
    int hh = blockIdx.y;
    int i = threadIdx.x;
    float inv = powf(1000000.0f, -(float)i / 64.0f);
    float f = (float)s * inv;
    float c = cosf(f), sn = sinf(f);
    float* base = (hh < NHEAD)
        ? q + (size_t)s * HID + hh * HDIM
        : k + (size_t)s * (NKVH * HDIM) + (hh - NHEAD) * HDIM;
    float x1 = base[i];
    float x2 = base[i + 64];
    base[i]      = x1 * c - x2 * sn;
    base[i + 64] = x2 * c + x1 * sn;
}

// ---------------- flash attention (fp32 SIMT, causal, GQA) ----------------
#define LDQ 132
#define ATTN_SMEM ((3 * 64 * LDQ + 64 * 65 + 3 * 64) * 4)

__global__ __launch_bounds__(256) void attn_kernel(
    const float* __restrict__ q, const float* __restrict__ k,
    const float* __restrict__ v, float* __restrict__ o) {
    extern __shared__ float smf[];
    float* Qs   = smf;
    float* Ks   = Qs + 64 * LDQ;
    float* Vs   = Ks + 64 * LDQ;
    float* Ss   = Vs + 64 * LDQ;
    float* Mrow = Ss + 64 * 65;
    float* Lrow = Mrow + 64;
    float* Arow = Lrow + 64;

    const int head = blockIdx.x;
    const int qb   = blockIdx.y;
    const int kvh  = head >> 2;
    const int tid  = threadIdx.x;

    for (int i = tid; i < 64 * 32; i += 256) {
        int r = i >> 5, c4 = (i & 31) << 2;
        *(float4*)(Qs + r * LDQ + c4) =
            *(const float4*)(q + (size_t)(qb * 64 + r) * HID + head * HDIM + c4);
    }
    if (tid < 64) { Mrow[tid] = -1e30f; Lrow[tid] = 0.f; }

    float acc[4][8];
#pragma unroll
    for (int i = 0; i < 4; i++)
#pragma unroll
        for (int j = 0; j < 8; j++) acc[i][j] = 0.f;

    const int i0 = (tid >> 4) * 4;
    const int j0 = (tid & 15) * 4;
    const int d0 = (tid & 15) * 8;
    const float scale = 0.08838834764831845f;

    for (int kb = 0; kb <= qb; kb++) {
        __syncthreads();
        for (int i = tid; i < 64 * 32; i += 256) {
            int r = i >> 5, c4 = (i & 31) << 2;
            size_t off = (size_t)(kb * 64 + r) * (NKVH * HDIM) + kvh * HDIM + c4;
            *(float4*)(Ks + r * LDQ + c4) = *(const float4*)(k + off);
            *(float4*)(Vs + r * LDQ + c4) = *(const float4*)(v + off);
        }
        __syncthreads();

        float sc[4][4];
#pragma unroll
        for (int a = 0; a < 4; a++)
#pragma unroll
            for (int b = 0; b < 4; b++) sc[a][b] = 0.f;
        for (int d4 = 0; d4 < HDIM; d4 += 4) {
            float4 qv[4], kv[4];
#pragma unroll
            for (int a = 0; a < 4; a++) qv[a] = *(const float4*)(Qs + (i0 + a) * LDQ + d4);
#pragma unroll
            for (int b = 0; b < 4; b++) kv[b] = *(const float4*)(Ks + (j0 + b) * LDQ + d4);
#pragma unroll
            for (int a = 0; a < 4; a++)
#pragma unroll
                for (int b = 0; b < 4; b++)
                    sc[a][b] += qv[a].x * kv[b].x + qv[a].y * kv[b].y
                              + qv[a].z * kv[b].z + qv[a].w * kv[b].w;
        }
#pragma unroll
        for (int a = 0; a < 4; a++)
#pragma unroll
            for (int b = 0; b < 4; b++) {
                float val = sc[a][b] * scale;
                if (kb == qb && (j0 + b) > (i0 + a)) val = -1e9f;
                Ss[(i0 + a) * 65 + (j0 + b)] = val;
            }
        __syncthreads();

        if (tid < 64) {
            int i = tid;
            float m = Mrow[i];
            float mb = -1e30f;
            for (int j = 0; j < 64; j++) mb = fmaxf(mb, Ss[i * 65 + j]);
            float mn = fmaxf(m, mb);
            float a = expf(m - mn);
            float s = 0.f;
            for (int j = 0; j < 64; j++) {
                float p = expf(Ss[i * 65 + j] - mn);
                Ss[i * 65 + j] = p;
                s += p;
            }
            Lrow[i] = Lrow[i] * a + s;
            Mrow[i] = mn;
            Arow[i] = a;
        }
        __syncthreads();

#pragma unroll
        for (int a = 0; a < 4; a++) {
            float al = Arow[i0 + a];
#pragma unroll
            for (int d = 0; d < 8; d++) acc[a][d] *= al;
        }
        for (int j = 0; j < 64; j++) {
            float4 v0 = *(const float4*)(Vs + j * LDQ + d0);
            float4 v1 = *(const float4*)(Vs + j * LDQ + d0 + 4);
#pragma unroll
            for (int a = 0; a < 4; a++) {
                float p = Ss[(i0 + a) * 65 + j];
                acc[a][0] += p * v0.x; acc[a][1] += p * v0.y;
                acc[a][2] += p * v0.z; acc[a][3] += p * v0.w;
                acc[a][4] += p * v1.x; acc[a][5] += p * v1.y;
                acc[a][6] += p * v1.z; acc[a][7] += p * v1.w;
            }
        }
    }

#pragma unroll
    for (int a = 0; a < 4; a++) {
        float linv = 1.0f / Lrow[i0 + a];
        int row = qb * 64 + i0 + a;
        float4 o0, o1;
        o0.x = acc[a][0] * linv; o0.y = acc[a][1] * linv;
        o0.z = acc[a][2] * linv; o0.w = acc[a][3] * linv;
        o1.x = acc[a][4] * linv; o1.y = acc[a][5] * linv;
        o1.z = acc[a][6] * linv; o1.w = acc[a][7] * linv;
        *(float4*)(o + (size_t)row * HID + head * HDIM + d0)     = o0;
        *(float4*)(o + (size_t)row * HID + head * HDIM + d0 + 4) = o1;
    }
}

// ---------------- SiLU(g) * u -> g ----------------
__global__ void silu_mul_kernel(float* __restrict__ g, const float* __restrict__ u) {
    int i = blockIdx.x * blockDim.x + threadIdx.x;
    float4 gv = ((const float4*)g)[i];
    float4 uv = ((const float4*)u)[i];
    gv.x = gv.x / (1.f + expf(-gv.x)) * uv.x;
    gv.y = gv.y / (1.f + expf(-gv.y)) * uv.y;
    gv.z = gv.z / (1.f + expf(-gv.z)) * uv.z;
    gv.w = gv.w / (1.f + expf(-gv.w)) * uv.w;
    ((float4*)g)[i] = gv;
}

// ---------------- host orchestration ----------------
static __nv_bfloat16 *s_ahi, *s_alo, *s_whi, *s_wlo;

static void run_split(const float* src, __nv_bfloat16* hi, __nv_bfloat16* lo,
                      size_t n) {
    int n4 = (int)(n / 4);
    split_kernel<<<(n4 + 255) / 256, 256>>>(src, hi, lo, n4);
}

static void run_gemm(const float* bias, const float* res, float* C,
                     int M, int N, int K) {
    if (N >= 2048) {
        dim3 grid(N / 128, M / 256);
        gemm_ps_kernel<256, 3><<<grid, 512, 181248>>>(
            s_ahi, s_alo, s_whi, s_wlo, bias, res, C, M, N, K);
    } else {
        dim3 grid(N / 128, M / 128);
        gemm_ps_kernel<128, 2><<<grid, 256, 79872>>>(
            s_ahi, s_alo, s_whi, s_wlo, bias, res, C, M, N, K);
    }
}

extern "C" void kernel_launch(void* const* d_in, const int* in_sizes, int n_in,
                              void* d_out, int out_size) {
    const int*   ids    = (const int*)d_in[0];
    const float* emb    = (const float*)d_in[1];
    const float* Wq     = (const float*)d_in[2];
    const float* bq     = (const float*)d_in[3];
    const float* Wk     = (const float*)d_in[4];
    const float* bk     = (const float*)d_in[5];
    const float* Wv     = (const float*)d_in[6];
    const float* bv     = (const float*)d_in[7];
    const float* Wo     = (const float*)d_in[8];
    const float* ln1    = (const float*)d_in[9];
    const float* ln2    = (const float*)d_in[10];
    const float* Wg     = (const float*)d_in[11];
    const float* Wu     = (const float*)d_in[12];
    const float* Wd     = (const float*)d_in[13];
    const float* norm_w = (const float*)d_in[14];
    const float* Wlm    = (const float*)d_in[15];
    const float* blm    = (const float*)d_in[16];
    float* out = (float*)d_out;

    float* base = nullptr;
    cudaGetSymbolAddress((void**)&base, g_scratch);
    cudaGetSymbolAddress((void**)&s_ahi, g_ahi);
    cudaGetSymbolAddress((void**)&s_alo, g_alo);
    cudaGetSymbolAddress((void**)&s_whi, g_whi);
    cudaGetSymbolAddress((void**)&s_wlo, g_wlo);

    float* hbuf = base;
    float* xbuf = base + (size_t)SH;
    float* qbuf = base + (size_t)2 * SH;
    float* abuf = base + (size_t)3 * SH;
    float* kbuf = base + (size_t)4 * SH;
    float* vbuf = kbuf + (size_t)SKV;
    float* gbuf = vbuf + (size_t)SKV;
    float* ubuf = gbuf + (size_t)SFF;

    cudaFuncSetAttribute(attn_kernel, cudaFuncAttributeMaxDynamicSharedMemorySize,
                         ATTN_SMEM);
    cudaFuncSetAttribute(gemm_ps_kernel<128, 2>,
                         cudaFuncAttributeMaxDynamicSharedMemorySize, 79872);
    cudaFuncSetAttribute(gemm_ps_kernel<256, 3>,
                         cudaFuncAttributeMaxDynamicSharedMemorySize, 181248);

    embed_kernel<<<SH / 4 / 256, 256>>>(ids, emb, hbuf);

    for (int l = 0; l < NLAYER; l++) {
        const float* Wql = Wq + (size_t)l * HID * HID;
        const float* bql = bq + (size_t)l * HID;
        const float* Wkl = Wk + (size_t)l * HID * (NKVH * HDIM);
        const float* bkl = bk + (size_t)l * (NKVH * HDIM);
        const float* Wvl = Wv + (size_t)l * HID * (NKVH * HDIM);
        const float* bvl = bv + (size_t)l * (NKVH * HDIM);
        const float* Wol = Wo + (size_t)l * HID * HID;
        const float* l1  = ln1 + (size_t)l * HID;
        const float* l2  = ln2 + (size_t)l * HID;
        const float* Wgl = Wg + (size_t)l * HID * FFD;
        const float* Wul = Wu + (size_t)l * HID * FFD;
        const float* Wdl = Wd + (size_t)l * FFD * HID;

        rmsnorm_kernel<<<SQ, 256>>>(hbuf, l1, xbuf);
        run_split(xbuf, s_ahi, s_alo, SH);
        run_split(Wql, s_whi, s_wlo, (size_t)HID * HID);
        run_gemm(bql, nullptr, qbuf, SQ, HID, HID);
        run_split(Wkl, s_whi, s_wlo, (size_t)HID * NKVH * HDIM);
        run_gemm(bkl, nullptr, kbuf, SQ, NKVH * HDIM, HID);
        run_split(Wvl, s_whi, s_wlo, (size_t)HID * NKVH * HDIM);
        run_gemm(bvl, nullptr, vbuf, SQ, NKVH * HDIM, HID);

        dim3 rgrid(SQ, NHEAD + NKVH);
        rope_kernel<<<rgrid, 64>>>(qbuf, kbuf);

        dim3 agrid(NHEAD, SQ / 64);
        attn_kernel<<<agrid, 256, ATTN_SMEM>>>(qbuf, kbuf, vbuf, abuf);

        run_split(abuf, s_ahi, s_alo, SH);
        run_split(Wol, s_whi, s_wlo, (size_t)HID * HID);
        run_gemm(nullptr, hbuf, hbuf, SQ, HID, HID);

        rmsnorm_kernel<<<SQ, 256>>>(hbuf, l2, xbuf);
        run_split(xbuf, s_ahi, s_alo, SH);
        run_split(Wgl, s_whi, s_wlo, (size_t)HID * FFD);
        run_gemm(nullptr, nullptr, gbuf, SQ, FFD, HID);
        run_split(Wul, s_whi, s_wlo, (size_t)HID * FFD);
        run_gemm(nullptr, nullptr, ubuf, SQ, FFD, HID);
        silu_mul_kernel<<<SFF / 4 / 256, 256>>>(gbuf, ubuf);
        run_split(gbuf, s_ahi, s_alo, SFF);
        run_split(Wdl, s_whi, s_wlo, (size_t)FFD * HID);
        run_gemm(nullptr, hbuf, hbuf, SQ, HID, FFD);
    }

    rmsnorm_kernel<<<SQ, 256>>>(hbuf, norm_w, xbuf);
    run_split(xbuf, s_ahi, s_alo, SH);
    run_split(Wlm, s_whi, s_wlo, (size_t)HID * VOC);
    run_gemm(blm, nullptr, out, SQ, VOC, HID);
}